// round 2
// baseline (speedup 1.0000x reference)
#include <cuda_runtime.h>
#include <math.h>

#define PAD   30
#define IMGS  224
#define CROPN 164
#define NB    16
#define NT    16

// PyTorch-style bilinear (align_corners=False) 1D index/weight,
// exactly matching the reference _interp1d.
__device__ __forceinline__ void interp1(float pos, float in_size, int out_size,
                                        int max_i, int& i0, int& i1, float& w) {
    float scale = in_size / (float)out_size;
    float f = fmaxf((pos + 0.5f) * scale - 0.5f, 0.0f);
    i0 = (int)floorf(f);
    w  = f - (float)i0;
    i1 = min(i0 + 1, max_i);
}

__global__ __launch_bounds__(256)
void prompt_add_kernel(
    const float* __restrict__ x,
    const float* __restrict__ pu,   // [3,3,60,224]
    const float* __restrict__ pd,   // [3,3,30,224]
    const float* __restrict__ pl,   // [3,3,164,60]
    const float* __restrict__ pr,   // [3,3,164,30]
    const int*   __restrict__ cam_views,
    const int*   __restrict__ offs_r,
    const int*   __restrict__ offs_d,
    float* __restrict__ out)
{
    const int J4 = IMGS / 4;                    // 56 float4 per row
    const int total = NB * 3 * IMGS * J4;
    int tid = blockIdx.x * blockDim.x + threadIdx.x;
    if (tid >= total) return;

    int j4 = tid % J4;
    int r  = tid / J4;
    int i  = r % IMGS; r /= IMGS;
    int c  = r % 3;
    int b  = r / 3;

    int cam   = __ldg(&cam_views[b]);
    int off_r = __ldg(&offs_r[b]);
    int off_d = __ldg(&offs_d[b]);
    int off_l = 2 * PAD - off_r;
    int off_u = 2 * PAD - off_d;
    int j     = j4 * 4;
    int cc    = cam * 3 + c;

    float4 pv;
    if (i < off_u) {
        // vertical top: interpolate two pad_up rows
        int r0, r1; float w;
        interp1((float)i, 2.0f * PAD, off_u, 2 * PAD - 1, r0, r1, w);
        const float4 a  = *(const float4*)(pu + ((size_t)cc * (2 * PAD) + r0) * IMGS + j);
        const float4 bq = *(const float4*)(pu + ((size_t)cc * (2 * PAD) + r1) * IMGS + j);
        float omw = 1.0f - w;
        pv.x = a.x * omw + bq.x * w;
        pv.y = a.y * omw + bq.y * w;
        pv.z = a.z * omw + bq.z * w;
        pv.w = a.w * omw + bq.w * w;
    } else if (i >= IMGS - off_d) {
        // vertical bottom: interpolate two pad_down rows
        int r0, r1; float w;
        interp1((float)(i - (IMGS - off_d)), (float)PAD, off_d, PAD - 1, r0, r1, w);
        const float4 a  = *(const float4*)(pd + ((size_t)cc * PAD + r0) * IMGS + j);
        const float4 bq = *(const float4*)(pd + ((size_t)cc * PAD + r1) * IMGS + j);
        float omw = 1.0f - w;
        pv.x = a.x * omw + bq.x * w;
        pv.y = a.y * omw + bq.y * w;
        pv.z = a.z * omw + bq.z * w;
        pv.w = a.w * omw + bq.w * w;
    } else {
        // middle rows: horizontal interp from pad_left / pad_right (or zero)
        int row = i - off_u;                    // 0..163
        const float* lrow = pl + ((size_t)cc * CROPN + row) * (2 * PAD);
        const float* rrow = pr + ((size_t)cc * CROPN + row) * PAD;
        float pp[4];
        #pragma unroll
        for (int k = 0; k < 4; k++) {
            int jj = j + k;
            if (jj < off_l) {
                int c0, c1; float w;
                interp1((float)jj, 2.0f * PAD, off_l, 2 * PAD - 1, c0, c1, w);
                pp[k] = lrow[c0] * (1.0f - w) + lrow[c1] * w;
            } else if (jj >= IMGS - off_r) {
                int c0, c1; float w;
                interp1((float)(jj - (IMGS - off_r)), (float)PAD, off_r, PAD - 1, c0, c1, w);
                pp[k] = rrow[c0] * (1.0f - w) + rrow[c1] * w;
            } else {
                pp[k] = 0.0f;
            }
        }
        pv = make_float4(pp[0], pp[1], pp[2], pp[3]);
    }

    // amortize the prompt over all T frames: 16x (float4 load + add + store)
    const size_t plane = (size_t)IMGS * IMGS;
    size_t base = ((size_t)(b * 3 + c) * NT) * plane + (size_t)i * IMGS + j;
    #pragma unroll
    for (int t = 0; t < NT; t++) {
        size_t off = base + (size_t)t * plane;
        float4 v = *(const float4*)(x + off);
        v.x += pv.x;
        v.y += pv.y;
        v.z += pv.z;
        v.w += pv.w;
        *(float4*)(out + off) = v;
    }
}

extern "C" void kernel_launch(void* const* d_in, const int* in_sizes, int n_in,
                              void* d_out, int out_size) {
    const float* x  = (const float*)d_in[0];
    const float* pu = (const float*)d_in[1];
    const float* pd = (const float*)d_in[2];
    const float* pl = (const float*)d_in[3];
    const float* pr = (const float*)d_in[4];
    const int* cam  = (const int*)d_in[5];
    const int* orr  = (const int*)d_in[6];
    const int* od   = (const int*)d_in[7];
    float* out = (float*)d_out;

    const int total = NB * 3 * IMGS * (IMGS / 4);   // 602112
    int block = 256;
    int grid = (total + block - 1) / block;
    prompt_add_kernel<<<grid, block>>>(x, pu, pd, pl, pr, cam, orr, od, out);
}